// round 14
// baseline (speedup 1.0000x reference)
#include <cuda_runtime.h>

#define N_NODES 100000
#define N_EDGES 800000
#define IN_DIM 128
#define HID_DIM 256
#define OUT_DIM 40

// ---------------- scratch (static __device__ arrays; no allocs) ----------------
__device__ float4 g_agg1[N_NODES * IN_DIM / 4];    // 51.2 MB  neighbor-sum of x
__device__ float4 g_h[N_NODES * HID_DIM / 4];      // 102.4 MB hidden activations
__device__ float4 g_pq[N_NODES * 2 * OUT_DIM / 4]; // 32 MB    [p = h@W2l | q = h@W2r]
__device__ float4 g_agg2[N_NODES * OUT_DIM / 4];   // 16 MB    neighbor-sum of p
__device__ float  g_inv[N_NODES];                  // 1/max(deg,1)
__device__ int    g_cnt[N_NODES];

// ---------------- tf32 helpers ----------------
__device__ __forceinline__ void tf32_split(float x, float& h, float& l) {
    unsigned hu, lu;
    asm("cvt.rna.tf32.f32 %0, %1;" : "=r"(hu) : "f"(x));
    float hf = __uint_as_float(hu);  // tf32 pattern is a valid fp32
    float d = x - hf;                // exact residual
    asm("cvt.rna.tf32.f32 %0, %1;" : "=r"(lu) : "f"(d));
    h = hf;
    l = __uint_as_float(lu);
}

__device__ __forceinline__ void mma_tf32(float* c, const unsigned* a, const unsigned* b) {
    asm volatile(
        "mma.sync.aligned.m16n8k8.row.col.f32.tf32.tf32.f32 "
        "{%0,%1,%2,%3}, {%4,%5,%6,%7}, {%8,%9}, {%0,%1,%2,%3};"
        : "+f"(c[0]), "+f"(c[1]), "+f"(c[2]), "+f"(c[3])
        : "r"(a[0]), "r"(a[1]), "r"(a[2]), "r"(a[3]), "r"(b[0]), "r"(b[1]));
}

__device__ __forceinline__ void red_add_v4(float* addr, float4 v) {
    asm volatile("red.global.add.v4.f32 [%0], {%1,%2,%3,%4};"
                 :: "l"(addr), "f"(v.x), "f"(v.y), "f"(v.z), "f"(v.w) : "memory");
}

// paired-layout SMEM stride (float4 units): 12 -> 48 floats, conflict-free phases
#define PSTR 12

// ---------------- zero scratch ----------------
__global__ void k_zero() {
    int i = blockIdx.x * blockDim.x + threadIdx.x;
    float4 z = make_float4(0.f, 0.f, 0.f, 0.f);
    if (i < N_NODES * IN_DIM / 4) g_agg1[i] = z;
    if (i < N_NODES * OUT_DIM / 4) g_agg2[i] = z;
    if (i < N_NODES) g_cnt[i] = 0;
}

// ---------------- edge pass 1: scatter-add x[src] -> agg1[dst], degree count ----------------
__global__ void k_edge1(const float4* __restrict__ x4, const int* __restrict__ ei) {
    int idx = blockIdx.x * blockDim.x + threadIdx.x;
    if (idx >= N_EDGES * 32) return;
    int e = idx >> 5;
    int c = idx & 31;
    int s = __ldg(&ei[e]);
    int d = __ldg(&ei[N_EDGES + e]);
    float4 v = x4[(size_t)s * 32 + c];
    float* a = ((float*)g_agg1) + (size_t)d * IN_DIM + c * 4;
    red_add_v4(a, v);
    if (c == 0) atomicAdd(&g_cnt[d], 1);
}

__global__ void k_inv() {
    int i = blockIdx.x * blockDim.x + threadIdx.x;
    if (i < N_NODES) g_inv[i] = 1.0f / fmaxf((float)g_cnt[i], 1.0f);
}

// ---------------- GEMM1 (tensor): h = relu((agg1*inv)@W1l + x@W1r + b1) ----------------
// BM=128, BN=64, BK=16. 256 threads = 8 warps (4m x 2n), warp tile 32x32.
// Fragment-major paired SMEM: one LDS.128 = (hi[k], lo[k], hi[k+4], lo[k+4]).
__global__ __launch_bounds__(256) void k_gemm1(const float4* __restrict__ x4,
                                               const float4* __restrict__ W1l4,
                                               const float4* __restrict__ W1r4,
                                               const float4* __restrict__ b14) {
    __shared__ __align__(16) float4 As_p[128][PSTR];  // 24KB (8 pk slots used)
    __shared__ __align__(16) float4 Bs_p[64][PSTR];   // 12KB (n-major!)

    int tid = threadIdx.x;
    int wid = tid >> 5, lane = tid & 31;
    int gid = lane >> 2, tig = lane & 3;
    int rowBase = blockIdx.y * 128;
    int colBase = blockIdx.x * 64;
    int warpM = (wid >> 1) * 32;
    int warpN = (wid & 1) * 32;

    float acc[2][4][4];
#pragma unroll
    for (int mt = 0; mt < 2; mt++)
#pragma unroll
        for (int nt = 0; nt < 4; nt++)
#pragma unroll
            for (int i = 0; i < 4; i++) acc[mt][nt][i] = 0.f;

#pragma unroll
    for (int phase = 0; phase < 2; ++phase) {
        const float4* A4 = phase ? x4 : g_agg1;
        const float4* W4 = phase ? W1r4 : W1l4;
        for (int kt = 0; kt < IN_DIM; kt += 16) {
            // stage A: idx -> (row r, float4-chunk q). k_local = q*4+j.
            // pk = (q>>1)*4 + j ; comp offset = (q&1)*2  -> (hi,lo) float2 store
#pragma unroll
            for (int i = 0; i < 2; i++) {
                int idx = tid + i * 256;
                int r = idx >> 2, q = idx & 3;
                int arow = rowBase + r;
                float4 v = make_float4(0.f, 0.f, 0.f, 0.f);
                if (arow < N_NODES) {
                    v = A4[(size_t)arow * 32 + (kt >> 2) + q];
                    if (phase == 0) {
                        float sc = g_inv[arow];
                        v.x *= sc; v.y *= sc; v.z *= sc; v.w *= sc;
                    }
                }
                int pkb = (q >> 1) * 4;
                int off = (q & 1) * 2;
                float h, l;
                tf32_split(v.x, h, l);
                *(float2*)((float*)&As_p[r][pkb + 0] + off) = make_float2(h, l);
                tf32_split(v.y, h, l);
                *(float2*)((float*)&As_p[r][pkb + 1] + off) = make_float2(h, l);
                tf32_split(v.z, h, l);
                *(float2*)((float*)&As_p[r][pkb + 2] + off) = make_float2(h, l);
                tf32_split(v.w, h, l);
                *(float2*)((float*)&As_p[r][pkb + 3] + off) = make_float2(h, l);
            }
            // stage B: 16 k x 16 float4 (64 n). n-major paired layout.
            {
                int k = tid >> 4, c4 = tid & 15;
                float4 w = W4[(size_t)(kt + k) * 64 + (colBase >> 2) + c4];
                int pk = (k & 3) + ((k >> 3) << 2);
                int off = (k & 4) ? 2 : 0;
                int nb = c4 * 4;
                float h, l;
                tf32_split(w.x, h, l);
                *(float2*)((float*)&Bs_p[nb + 0][pk] + off) = make_float2(h, l);
                tf32_split(w.y, h, l);
                *(float2*)((float*)&Bs_p[nb + 1][pk] + off) = make_float2(h, l);
                tf32_split(w.z, h, l);
                *(float2*)((float*)&Bs_p[nb + 2][pk] + off) = make_float2(h, l);
                tf32_split(w.w, h, l);
                *(float2*)((float*)&Bs_p[nb + 3][pk] + off) = make_float2(h, l);
            }
            __syncthreads();
#pragma unroll
            for (int s = 0; s < 2; s++) {
                int pk = s * 4 + tig;   // k0 = s*8 + tig, pairs (k0, k0+4)
                unsigned ah[8], al[8], bh[8], bl[8];
#pragma unroll
                for (int mt = 0; mt < 2; mt++) {
                    int m0 = warpM + mt * 16 + gid;
                    float4 v1 = As_p[m0][pk];
                    float4 v2 = As_p[m0 + 8][pk];
                    ah[mt*4+0] = __float_as_uint(v1.x);
                    ah[mt*4+1] = __float_as_uint(v2.x);
                    ah[mt*4+2] = __float_as_uint(v1.z);
                    ah[mt*4+3] = __float_as_uint(v2.z);
                    al[mt*4+0] = __float_as_uint(v1.y);
                    al[mt*4+1] = __float_as_uint(v2.y);
                    al[mt*4+2] = __float_as_uint(v1.w);
                    al[mt*4+3] = __float_as_uint(v2.w);
                }
#pragma unroll
                for (int nt = 0; nt < 4; nt++) {
                    int n0 = warpN + nt * 8 + gid;
                    float4 v = Bs_p[n0][pk];
                    bh[nt*2+0] = __float_as_uint(v.x);
                    bh[nt*2+1] = __float_as_uint(v.z);
                    bl[nt*2+0] = __float_as_uint(v.y);
                    bl[nt*2+1] = __float_as_uint(v.w);
                }
#pragma unroll
                for (int mt = 0; mt < 2; mt++)
#pragma unroll
                    for (int nt = 0; nt < 4; nt++) {
                        float* c = acc[mt][nt];
                        mma_tf32(c, &ah[mt * 4], &bh[nt * 2]);  // hi*hi
                        mma_tf32(c, &ah[mt * 4], &bl[nt * 2]);  // hi*lo
                        mma_tf32(c, &al[mt * 4], &bh[nt * 2]);  // lo*hi
                    }
            }
            __syncthreads();
        }
    }

    // epilogue: bias + relu, float2 stores
#pragma unroll
    for (int mt = 0; mt < 2; mt++) {
#pragma unroll
        for (int nt = 0; nt < 4; nt++) {
            int r0 = rowBase + warpM + mt * 16 + gid;
            int col = colBase + warpN + nt * 8 + 2 * tig;
            float2 bb = *(const float2*)((const float*)b14 + col);
            const float* c = acc[mt][nt];
            if (r0 < N_NODES) {
                float2 o = make_float2(fmaxf(c[0] + bb.x, 0.f), fmaxf(c[1] + bb.y, 0.f));
                *(float2*)(((float*)g_h) + (size_t)r0 * HID_DIM + col) = o;
            }
            if (r0 + 8 < N_NODES) {
                float2 o = make_float2(fmaxf(c[2] + bb.x, 0.f), fmaxf(c[3] + bb.y, 0.f));
                *(float2*)(((float*)g_h) + (size_t)(r0 + 8) * HID_DIM + col) = o;
            }
        }
    }
}

// ---------------- GEMM2 (tensor): pq = h @ [W2l | W2r]  (N x 80, K=256) ----------------
// BM=128, BN=80, BK=16. 256 threads = 8 warps (4m x 2n), warp tile 32x40.
__global__ __launch_bounds__(256) void k_gemm2(const float4* __restrict__ W2l4,
                                               const float4* __restrict__ W2r4) {
    __shared__ __align__(16) float4 As_p[128][PSTR];  // 24KB
    __shared__ __align__(16) float4 Bs_p[80][PSTR];   // 15.4KB

    int tid = threadIdx.x;
    int wid = tid >> 5, lane = tid & 31;
    int gid = lane >> 2, tig = lane & 3;
    int rowBase = blockIdx.y * 128;
    int warpM = (wid >> 1) * 32;
    int warpN = (wid & 1) * 40;

    float acc[2][5][4];
#pragma unroll
    for (int mt = 0; mt < 2; mt++)
#pragma unroll
        for (int nt = 0; nt < 5; nt++)
#pragma unroll
            for (int i = 0; i < 4; i++) acc[mt][nt][i] = 0.f;

    for (int kt = 0; kt < HID_DIM; kt += 16) {
        // stage A from g_h
#pragma unroll
        for (int i = 0; i < 2; i++) {
            int idx = tid + i * 256;
            int r = idx >> 2, q = idx & 3;
            int arow = rowBase + r;
            float4 v = make_float4(0.f, 0.f, 0.f, 0.f);
            if (arow < N_NODES) v = g_h[(size_t)arow * 64 + (kt >> 2) + q];
            int pkb = (q >> 1) * 4;
            int off = (q & 1) * 2;
            float h, l;
            tf32_split(v.x, h, l);
            *(float2*)((float*)&As_p[r][pkb + 0] + off) = make_float2(h, l);
            tf32_split(v.y, h, l);
            *(float2*)((float*)&As_p[r][pkb + 1] + off) = make_float2(h, l);
            tf32_split(v.z, h, l);
            *(float2*)((float*)&As_p[r][pkb + 2] + off) = make_float2(h, l);
            tf32_split(v.w, h, l);
            *(float2*)((float*)&As_p[r][pkb + 3] + off) = make_float2(h, l);
        }
        // stage B: 16 k x 20 float4 ([W2l | W2r]) -> n-major paired
        for (int idx = tid; idx < 320; idx += 256) {
            int k = idx / 20, c4 = idx % 20;
            float4 w;
            if (c4 < 10) w = W2l4[(size_t)(kt + k) * 10 + c4];
            else         w = W2r4[(size_t)(kt + k) * 10 + (c4 - 10)];
            int pk = (k & 3) + ((k >> 3) << 2);
            int off = (k & 4) ? 2 : 0;
            int nb = c4 * 4;
            float h, l;
            tf32_split(w.x, h, l);
            *(float2*)((float*)&Bs_p[nb + 0][pk] + off) = make_float2(h, l);
            tf32_split(w.y, h, l);
            *(float2*)((float*)&Bs_p[nb + 1][pk] + off) = make_float2(h, l);
            tf32_split(w.z, h, l);
            *(float2*)((float*)&Bs_p[nb + 2][pk] + off) = make_float2(h, l);
            tf32_split(w.w, h, l);
            *(float2*)((float*)&Bs_p[nb + 3][pk] + off) = make_float2(h, l);
        }
        __syncthreads();
#pragma unroll
        for (int s = 0; s < 2; s++) {
            int pk = s * 4 + tig;
            unsigned ah[8], al[8], bh[10], bl[10];
#pragma unroll
            for (int mt = 0; mt < 2; mt++) {
                int m0 = warpM + mt * 16 + gid;
                float4 v1 = As_p[m0][pk];
                float4 v2 = As_p[m0 + 8][pk];
                ah[mt*4+0] = __float_as_uint(v1.x);
                ah[mt*4+1] = __float_as_uint(v2.x);
                ah[mt*4+2] = __float_as_uint(v1.z);
                ah[mt*4+3] = __float_as_uint(v2.z);
                al[mt*4+0] = __float_as_uint(v1.y);
                al[mt*4+1] = __float_as_uint(v2.y);
                al[mt*4+2] = __float_as_uint(v1.w);
                al[mt*4+3] = __float_as_uint(v2.w);
            }
#pragma unroll
            for (int nt = 0; nt < 5; nt++) {
                int n0 = warpN + nt * 8 + gid;
                float4 v = Bs_p[n0][pk];
                bh[nt*2+0] = __float_as_uint(v.x);
                bh[nt*2+1] = __float_as_uint(v.z);
                bl[nt*2+0] = __float_as_uint(v.y);
                bl[nt*2+1] = __float_as_uint(v.w);
            }
#pragma unroll
            for (int mt = 0; mt < 2; mt++)
#pragma unroll
                for (int nt = 0; nt < 5; nt++) {
                    float* c = acc[mt][nt];
                    mma_tf32(c, &ah[mt * 4], &bh[nt * 2]);
                    mma_tf32(c, &ah[mt * 4], &bl[nt * 2]);
                    mma_tf32(c, &al[mt * 4], &bh[nt * 2]);
                }
        }
        __syncthreads();
    }

#pragma unroll
    for (int mt = 0; mt < 2; mt++) {
#pragma unroll
        for (int nt = 0; nt < 5; nt++) {
            int r0 = rowBase + warpM + mt * 16 + gid;
            int col = warpN + nt * 8 + 2 * tig;   // 0..79 within [p|q]
            const float* c = acc[mt][nt];
            if (r0 < N_NODES)
                *(float2*)(((float*)g_pq) + (size_t)r0 * 80 + col) = make_float2(c[0], c[1]);
            if (r0 + 8 < N_NODES)
                *(float2*)(((float*)g_pq) + (size_t)(r0 + 8) * 80 + col) = make_float2(c[2], c[3]);
        }
    }
}

// ---------------- edge pass 2: scatter-add p[src] -> agg2[dst] (40 floats) ----------------
__global__ void k_scatter2(const int* __restrict__ ei) {
    int idx = blockIdx.x * blockDim.x + threadIdx.x;
    if (idx >= N_EDGES * 10) return;
    int e = idx / 10;
    int c = idx % 10;
    int s = __ldg(&ei[e]);
    int d = __ldg(&ei[N_EDGES + e]);
    float4 v = g_pq[(size_t)s * 20 + c];  // p half = f4 slots 0..9
    float* a = ((float*)g_agg2) + (size_t)d * OUT_DIM + c * 4;
    red_add_v4(a, v);
}

// ---------------- finalize: out = agg2*inv + b2 + q ----------------
__global__ void k_final(const float4* __restrict__ b24, float4* __restrict__ out4) {
    int idx = blockIdx.x * blockDim.x + threadIdx.x;
    if (idx >= N_NODES * 10) return;
    int row = idx / 10;
    int c = idx % 10;
    float inv = g_inv[row];
    float4 ag = g_agg2[(size_t)row * 10 + c];
    float4 q = g_pq[(size_t)row * 20 + 10 + c];  // q half = f4 slots 10..19
    float4 b = b24[c];
    float4 o;
    o.x = ag.x * inv + b.x + q.x;
    o.y = ag.y * inv + b.y + q.y;
    o.z = ag.z * inv + b.z + q.z;
    o.w = ag.w * inv + b.w + q.w;
    out4[idx] = o;
}

// ---------------- launch ----------------
extern "C" void kernel_launch(void* const* d_in, const int* in_sizes, int n_in,
                              void* d_out, int out_size) {
    const float4* x4 = (const float4*)d_in[0];
    const int* ei = (const int*)d_in[1];   // int32 (JAX x64 disabled)
    const float4* W1l4 = (const float4*)d_in[2];
    const float4* b14 = (const float4*)d_in[3];
    const float4* W1r4 = (const float4*)d_in[4];
    const float4* W2l4 = (const float4*)d_in[5];
    const float4* b24 = (const float4*)d_in[6];
    const float4* W2r4 = (const float4*)d_in[7];
    float4* out4 = (float4*)d_out;

    k_zero<<<(N_NODES * IN_DIM / 4 + 255) / 256, 256>>>();
    k_edge1<<<(N_EDGES * 32 + 255) / 256, 256>>>(x4, ei);
    k_inv<<<(N_NODES + 255) / 256, 256>>>();
    dim3 g1(HID_DIM / 64, (N_NODES + 127) / 128);
    k_gemm1<<<g1, 256>>>(x4, W1l4, W1r4, b14);
    dim3 g2(1, (N_NODES + 127) / 128);
    k_gemm2<<<g2, 256>>>(W2l4, W2r4);
    k_scatter2<<<(N_EDGES * 10 + 255) / 256, 256>>>(ei);
    k_final<<<(N_NODES * 10 + 255) / 256, 256>>>(b24, out4);
}

// round 15
// speedup vs baseline: 1.4405x; 1.4405x over previous
#include <cuda_runtime.h>

#define N_NODES 100000
#define N_EDGES 800000
#define IN_DIM 128
#define HID_DIM 256
#define OUT_DIM 40

// ---------------- scratch (static __device__ arrays; no allocs) ----------------
__device__ float4 g_agg1[N_NODES * IN_DIM / 4];    // 51.2 MB  neighbor-sum of x
__device__ float4 g_h[N_NODES * HID_DIM / 4];      // 102.4 MB hidden activations
__device__ float4 g_pq[N_NODES * 2 * OUT_DIM / 4]; // 32 MB    [p = h@W2l | q = h@W2r]
__device__ float4 g_agg2[N_NODES * OUT_DIM / 4];   // 16 MB    neighbor-sum of p
__device__ float  g_inv[N_NODES];                  // 1/max(deg,1)
__device__ int    g_cnt[N_NODES];

// ---------------- tf32 helpers ----------------
__device__ __forceinline__ void tf32_split(float x, float& h, float& l) {
    unsigned hu, lu;
    asm("cvt.rna.tf32.f32 %0, %1;" : "=r"(hu) : "f"(x));
    float hf = __uint_as_float(hu);  // tf32 pattern is a valid fp32
    float d = x - hf;                // exact residual
    asm("cvt.rna.tf32.f32 %0, %1;" : "=r"(lu) : "f"(d));
    h = hf;
    l = __uint_as_float(lu);
}

__device__ __forceinline__ void mma_tf32(float* c, const unsigned* a, const unsigned* b) {
    asm volatile(
        "mma.sync.aligned.m16n8k8.row.col.f32.tf32.tf32.f32 "
        "{%0,%1,%2,%3}, {%4,%5,%6,%7}, {%8,%9}, {%0,%1,%2,%3};"
        : "+f"(c[0]), "+f"(c[1]), "+f"(c[2]), "+f"(c[3])
        : "r"(a[0]), "r"(a[1]), "r"(a[2]), "r"(a[3]), "r"(b[0]), "r"(b[1]));
}

__device__ __forceinline__ void red_add_v4(float* addr, float4 v) {
    asm volatile("red.global.add.v4.f32 [%0], {%1,%2,%3,%4};"
                 :: "l"(addr), "f"(v.x), "f"(v.y), "f"(v.z), "f"(v.w) : "memory");
}

// ---------------- zero scratch ----------------
__global__ void k_zero() {
    int i = blockIdx.x * blockDim.x + threadIdx.x;
    float4 z = make_float4(0.f, 0.f, 0.f, 0.f);
    if (i < N_NODES * IN_DIM / 4) g_agg1[i] = z;
    if (i < N_NODES * OUT_DIM / 4) g_agg2[i] = z;
    if (i < N_NODES) g_cnt[i] = 0;
}

// ---------------- edge pass 1: scatter-add x[src] -> agg1[dst], degree count ----------------
__global__ void k_edge1(const float4* __restrict__ x4, const int* __restrict__ ei) {
    int idx = blockIdx.x * blockDim.x + threadIdx.x;
    if (idx >= N_EDGES * 32) return;
    int e = idx >> 5;
    int c = idx & 31;
    int s = __ldg(&ei[e]);
    int d = __ldg(&ei[N_EDGES + e]);
    float4 v = x4[(size_t)s * 32 + c];
    float* a = ((float*)g_agg1) + (size_t)d * IN_DIM + c * 4;
    red_add_v4(a, v);
    if (c == 0) atomicAdd(&g_cnt[d], 1);
}

__global__ void k_inv() {
    int i = blockIdx.x * blockDim.x + threadIdx.x;
    if (i < N_NODES) g_inv[i] = 1.0f / fmaxf((float)g_cnt[i], 1.0f);
}

// ---------------- GEMM1 (tensor): h = relu((agg1*inv)@W1l + x@W1r + b1) ----------------
// BM=128, BN=128, BK=16. 256 threads = 8 warps (4m x 2n), warp tile 32x64.
// hi/lo planes in SMEM (R13 layout), nt processed in halves of 4 to bound regs.
__global__ __launch_bounds__(256) void k_gemm1(const float4* __restrict__ x4,
                                               const float4* __restrict__ W1l4,
                                               const float4* __restrict__ W1r4,
                                               const float4* __restrict__ b14) {
    __shared__ __align__(16) float As_hi[128][20], As_lo[128][20];   // 20KB
    __shared__ __align__(16) float Bs_hi[16][136], Bs_lo[16][136];   // 17.4KB

    int tid = threadIdx.x;
    int wid = tid >> 5, lane = tid & 31;
    int gid = lane >> 2, tig = lane & 3;
    int rowBase = blockIdx.y * 128;
    int colBase = blockIdx.x * 128;
    int warpM = (wid >> 1) * 32;
    int warpN = (wid & 1) * 64;

    float acc[2][8][4];
#pragma unroll
    for (int mt = 0; mt < 2; mt++)
#pragma unroll
        for (int nt = 0; nt < 8; nt++)
#pragma unroll
            for (int i = 0; i < 4; i++) acc[mt][nt][i] = 0.f;

#pragma unroll
    for (int phase = 0; phase < 2; ++phase) {
        const float4* A4 = phase ? x4 : g_agg1;
        const float4* W4 = phase ? W1r4 : W1l4;
        for (int kt = 0; kt < IN_DIM; kt += 16) {
            // stage A: 128 rows x 4 float4, split hi/lo, aligned STS.128
#pragma unroll
            for (int i = 0; i < 2; i++) {
                int idx = tid + i * 256;
                int r = idx >> 2, q = idx & 3;
                int arow = rowBase + r;
                float4 v = make_float4(0.f, 0.f, 0.f, 0.f);
                if (arow < N_NODES) {
                    v = A4[(size_t)arow * 32 + (kt >> 2) + q];
                    if (phase == 0) {
                        float sc = g_inv[arow];
                        v.x *= sc; v.y *= sc; v.z *= sc; v.w *= sc;
                    }
                }
                float h0, l0, h1, l1, h2, l2, h3, l3;
                tf32_split(v.x, h0, l0); tf32_split(v.y, h1, l1);
                tf32_split(v.z, h2, l2); tf32_split(v.w, h3, l3);
                int kb = q * 4;
                *(float4*)&As_hi[r][kb] = make_float4(h0, h1, h2, h3);
                *(float4*)&As_lo[r][kb] = make_float4(l0, l1, l2, l3);
            }
            // stage B: 16 k x 32 float4 (128 n cols)
#pragma unroll
            for (int i = 0; i < 2; i++) {
                int idx = tid + i * 256;
                int k = idx >> 5, c4 = idx & 31;
                float4 w = W4[(size_t)(kt + k) * 64 + (colBase >> 2) + c4];
                float h0, l0, h1, l1, h2, l2, h3, l3;
                tf32_split(w.x, h0, l0); tf32_split(w.y, h1, l1);
                tf32_split(w.z, h2, l2); tf32_split(w.w, h3, l3);
                int nb = c4 * 4;
                *(float4*)&Bs_hi[k][nb] = make_float4(h0, h1, h2, h3);
                *(float4*)&Bs_lo[k][nb] = make_float4(l0, l1, l2, l3);
            }
            __syncthreads();
#pragma unroll
            for (int s = 0; s < 2; s++) {
                int k0 = s * 8 + tig;
                unsigned ah[8], al[8];
#pragma unroll
                for (int mt = 0; mt < 2; mt++) {
                    int m0 = warpM + mt * 16 + gid;
                    ah[mt*4+0] = __float_as_uint(As_hi[m0][k0]);
                    ah[mt*4+1] = __float_as_uint(As_hi[m0 + 8][k0]);
                    ah[mt*4+2] = __float_as_uint(As_hi[m0][k0 + 4]);
                    ah[mt*4+3] = __float_as_uint(As_hi[m0 + 8][k0 + 4]);
                    al[mt*4+0] = __float_as_uint(As_lo[m0][k0]);
                    al[mt*4+1] = __float_as_uint(As_lo[m0 + 8][k0]);
                    al[mt*4+2] = __float_as_uint(As_lo[m0][k0 + 4]);
                    al[mt*4+3] = __float_as_uint(As_lo[m0 + 8][k0 + 4]);
                }
#pragma unroll
                for (int half = 0; half < 2; half++) {
                    unsigned bh[8], bl[8];
#pragma unroll
                    for (int j = 0; j < 4; j++) {
                        int n0 = warpN + (half * 4 + j) * 8 + gid;
                        bh[j*2+0] = __float_as_uint(Bs_hi[k0][n0]);
                        bh[j*2+1] = __float_as_uint(Bs_hi[k0 + 4][n0]);
                        bl[j*2+0] = __float_as_uint(Bs_lo[k0][n0]);
                        bl[j*2+1] = __float_as_uint(Bs_lo[k0 + 4][n0]);
                    }
#pragma unroll
                    for (int mt = 0; mt < 2; mt++)
#pragma unroll
                        for (int j = 0; j < 4; j++) {
                            float* c = acc[mt][half * 4 + j];
                            mma_tf32(c, &ah[mt * 4], &bh[j * 2]);  // hi*hi
                            mma_tf32(c, &ah[mt * 4], &bl[j * 2]);  // hi*lo
                            mma_tf32(c, &al[mt * 4], &bh[j * 2]);  // lo*hi
                        }
                }
            }
            __syncthreads();
        }
    }

    // epilogue: bias + relu, float2 stores
#pragma unroll
    for (int mt = 0; mt < 2; mt++) {
#pragma unroll
        for (int nt = 0; nt < 8; nt++) {
            int r0 = rowBase + warpM + mt * 16 + gid;
            int col = colBase + warpN + nt * 8 + 2 * tig;
            float2 bb = *(const float2*)((const float*)b14 + col);
            const float* c = acc[mt][nt];
            if (r0 < N_NODES) {
                float2 o = make_float2(fmaxf(c[0] + bb.x, 0.f), fmaxf(c[1] + bb.y, 0.f));
                *(float2*)(((float*)g_h) + (size_t)r0 * HID_DIM + col) = o;
            }
            if (r0 + 8 < N_NODES) {
                float2 o = make_float2(fmaxf(c[2] + bb.x, 0.f), fmaxf(c[3] + bb.y, 0.f));
                *(float2*)(((float*)g_h) + (size_t)(r0 + 8) * HID_DIM + col) = o;
            }
        }
    }
}

// ---------------- GEMM2 (tensor): pq = h @ [W2l | W2r]  (N x 80, K=256) ----------------
// BM=128, BN=80, BK=16. 256 threads = 8 warps (4m x 2n), warp tile 32x40. (R13 verbatim)
__global__ __launch_bounds__(256) void k_gemm2(const float4* __restrict__ W2l4,
                                               const float4* __restrict__ W2r4) {
    __shared__ __align__(16) float As_hi[128][20], As_lo[128][20];  // 20KB
    __shared__ __align__(16) float Bs_hi[16][88], Bs_lo[16][88];    // 11KB

    int tid = threadIdx.x;
    int wid = tid >> 5, lane = tid & 31;
    int gid = lane >> 2, tig = lane & 3;
    int rowBase = blockIdx.y * 128;
    int warpM = (wid >> 1) * 32;
    int warpN = (wid & 1) * 40;

    float acc[2][5][4];
#pragma unroll
    for (int mt = 0; mt < 2; mt++)
#pragma unroll
        for (int nt = 0; nt < 5; nt++)
#pragma unroll
            for (int i = 0; i < 4; i++) acc[mt][nt][i] = 0.f;

    for (int kt = 0; kt < HID_DIM; kt += 16) {
        // stage A from g_h (split at store, aligned STS.128)
#pragma unroll
        for (int i = 0; i < 2; i++) {
            int idx = tid + i * 256;
            int r = idx >> 2, q = idx & 3;
            int arow = rowBase + r;
            float4 v = make_float4(0.f, 0.f, 0.f, 0.f);
            if (arow < N_NODES) v = g_h[(size_t)arow * 64 + (kt >> 2) + q];
            float h0, l0, h1, l1, h2, l2, h3, l3;
            tf32_split(v.x, h0, l0); tf32_split(v.y, h1, l1);
            tf32_split(v.z, h2, l2); tf32_split(v.w, h3, l3);
            int kb = q * 4;
            *(float4*)&As_hi[r][kb] = make_float4(h0, h1, h2, h3);
            *(float4*)&As_lo[r][kb] = make_float4(l0, l1, l2, l3);
        }
        // stage B: 16 k x 20 float4 ([W2l | W2r])
        for (int idx = tid; idx < 320; idx += 256) {
            int k = idx / 20, c4 = idx % 20;
            float4 w;
            if (c4 < 10) w = W2l4[(size_t)(kt + k) * 10 + c4];
            else         w = W2r4[(size_t)(kt + k) * 10 + (c4 - 10)];
            float h0, l0, h1, l1, h2, l2, h3, l3;
            tf32_split(w.x, h0, l0); tf32_split(w.y, h1, l1);
            tf32_split(w.z, h2, l2); tf32_split(w.w, h3, l3);
            int nb = c4 * 4;
            *(float4*)&Bs_hi[k][nb] = make_float4(h0, h1, h2, h3);
            *(float4*)&Bs_lo[k][nb] = make_float4(l0, l1, l2, l3);
        }
        __syncthreads();
#pragma unroll
        for (int s = 0; s < 2; s++) {
            int k0 = s * 8 + tig;
            unsigned ah[8], al[8], bh[10], bl[10];
#pragma unroll
            for (int mt = 0; mt < 2; mt++) {
                int m0 = warpM + mt * 16 + gid;
                ah[mt*4+0] = __float_as_uint(As_hi[m0][k0]);
                ah[mt*4+1] = __float_as_uint(As_hi[m0 + 8][k0]);
                ah[mt*4+2] = __float_as_uint(As_hi[m0][k0 + 4]);
                ah[mt*4+3] = __float_as_uint(As_hi[m0 + 8][k0 + 4]);
                al[mt*4+0] = __float_as_uint(As_lo[m0][k0]);
                al[mt*4+1] = __float_as_uint(As_lo[m0 + 8][k0]);
                al[mt*4+2] = __float_as_uint(As_lo[m0][k0 + 4]);
                al[mt*4+3] = __float_as_uint(As_lo[m0 + 8][k0 + 4]);
            }
#pragma unroll
            for (int nt = 0; nt < 5; nt++) {
                int n0 = warpN + nt * 8 + gid;
                bh[nt*2+0] = __float_as_uint(Bs_hi[k0][n0]);
                bh[nt*2+1] = __float_as_uint(Bs_hi[k0 + 4][n0]);
                bl[nt*2+0] = __float_as_uint(Bs_lo[k0][n0]);
                bl[nt*2+1] = __float_as_uint(Bs_lo[k0 + 4][n0]);
            }
#pragma unroll
            for (int mt = 0; mt < 2; mt++)
#pragma unroll
                for (int nt = 0; nt < 5; nt++) {
                    float* c = acc[mt][nt];
                    mma_tf32(c, &ah[mt * 4], &bh[nt * 2]);
                    mma_tf32(c, &ah[mt * 4], &bl[nt * 2]);
                    mma_tf32(c, &al[mt * 4], &bh[nt * 2]);
                }
        }
        __syncthreads();
    }

#pragma unroll
    for (int mt = 0; mt < 2; mt++) {
#pragma unroll
        for (int nt = 0; nt < 5; nt++) {
            int r0 = rowBase + warpM + mt * 16 + gid;
            int col = warpN + nt * 8 + 2 * tig;   // 0..79 within [p|q]
            const float* c = acc[mt][nt];
            if (r0 < N_NODES)
                *(float2*)(((float*)g_pq) + (size_t)r0 * 80 + col) = make_float2(c[0], c[1]);
            if (r0 + 8 < N_NODES)
                *(float2*)(((float*)g_pq) + (size_t)(r0 + 8) * 80 + col) = make_float2(c[2], c[3]);
        }
    }
}

// ---------------- edge pass 2: scatter-add p[src] -> agg2[dst] (40 floats) ----------------
__global__ void k_scatter2(const int* __restrict__ ei) {
    int idx = blockIdx.x * blockDim.x + threadIdx.x;
    if (idx >= N_EDGES * 10) return;
    int e = idx / 10;
    int c = idx % 10;
    int s = __ldg(&ei[e]);
    int d = __ldg(&ei[N_EDGES + e]);
    float4 v = g_pq[(size_t)s * 20 + c];  // p half = f4 slots 0..9
    float* a = ((float*)g_agg2) + (size_t)d * OUT_DIM + c * 4;
    red_add_v4(a, v);
}

// ---------------- finalize: out = agg2*inv + b2 + q ----------------
__global__ void k_final(const float4* __restrict__ b24, float4* __restrict__ out4) {
    int idx = blockIdx.x * blockDim.x + threadIdx.x;
    if (idx >= N_NODES * 10) return;
    int row = idx / 10;
    int c = idx % 10;
    float inv = g_inv[row];
    float4 ag = g_agg2[(size_t)row * 10 + c];
    float4 q = g_pq[(size_t)row * 20 + 10 + c];  // q half = f4 slots 10..19
    float4 b = b24[c];
    float4 o;
    o.x = ag.x * inv + b.x + q.x;
    o.y = ag.y * inv + b.y + q.y;
    o.z = ag.z * inv + b.z + q.z;
    o.w = ag.w * inv + b.w + q.w;
    out4[idx] = o;
}

// ---------------- launch ----------------
extern "C" void kernel_launch(void* const* d_in, const int* in_sizes, int n_in,
                              void* d_out, int out_size) {
    const float4* x4 = (const float4*)d_in[0];
    const int* ei = (const int*)d_in[1];   // int32 (JAX x64 disabled)
    const float4* W1l4 = (const float4*)d_in[2];
    const float4* b14 = (const float4*)d_in[3];
    const float4* W1r4 = (const float4*)d_in[4];
    const float4* W2l4 = (const float4*)d_in[5];
    const float4* b24 = (const float4*)d_in[6];
    const float4* W2r4 = (const float4*)d_in[7];
    float4* out4 = (float4*)d_out;

    k_zero<<<(N_NODES * IN_DIM / 4 + 255) / 256, 256>>>();
    k_edge1<<<(N_EDGES * 32 + 255) / 256, 256>>>(x4, ei);
    k_inv<<<(N_NODES + 255) / 256, 256>>>();
    dim3 g1(HID_DIM / 128, (N_NODES + 127) / 128);   // 2 x 782
    k_gemm1<<<g1, 256>>>(x4, W1l4, W1r4, b14);
    dim3 g2(1, (N_NODES + 127) / 128);
    k_gemm2<<<g2, 256>>>(W2l4, W2r4);
    k_scatter2<<<(N_EDGES * 10 + 255) / 256, 256>>>(ei);
    k_final<<<(N_NODES * 10 + 255) / 256, 256>>>(b24, out4);
}

// round 16
// speedup vs baseline: 1.6811x; 1.1671x over previous
#include <cuda_runtime.h>

#define N_NODES 100000
#define N_EDGES 800000
#define IN_DIM 128
#define HID_DIM 256
#define OUT_DIM 40

// ---------------- scratch (static __device__ arrays; no allocs) ----------------
__device__ float4 g_agg1[N_NODES * IN_DIM / 4];    // 51.2 MB  neighbor-sum of x
__device__ float4 g_h[N_NODES * HID_DIM / 4];      // 102.4 MB hidden activations
__device__ float4 g_pq[N_NODES * 2 * OUT_DIM / 4]; // 32 MB    [p = h@W2l | q = h@W2r]
__device__ float4 g_agg2[N_NODES * OUT_DIM / 4];   // 16 MB    neighbor-sum of p
__device__ float  g_inv[N_NODES];                  // 1/max(deg,1)
__device__ int    g_cnt[N_NODES];

// ---------------- tf32 helpers ----------------
__device__ __forceinline__ void tf32_split(float x, float& h, float& l) {
    unsigned hu, lu;
    asm("cvt.rna.tf32.f32 %0, %1;" : "=r"(hu) : "f"(x));
    float hf = __uint_as_float(hu);  // tf32 pattern is a valid fp32
    float d = x - hf;                // exact residual
    asm("cvt.rna.tf32.f32 %0, %1;" : "=r"(lu) : "f"(d));
    h = hf;
    l = __uint_as_float(lu);
}

__device__ __forceinline__ void mma_tf32(float* c, const unsigned* a, const unsigned* b) {
    asm volatile(
        "mma.sync.aligned.m16n8k8.row.col.f32.tf32.tf32.f32 "
        "{%0,%1,%2,%3}, {%4,%5,%6,%7}, {%8,%9}, {%0,%1,%2,%3};"
        : "+f"(c[0]), "+f"(c[1]), "+f"(c[2]), "+f"(c[3])
        : "r"(a[0]), "r"(a[1]), "r"(a[2]), "r"(a[3]), "r"(b[0]), "r"(b[1]));
}

__device__ __forceinline__ void red_add_v4(float* addr, float4 v) {
    asm volatile("red.global.add.v4.f32 [%0], {%1,%2,%3,%4};"
                 :: "l"(addr), "f"(v.x), "f"(v.y), "f"(v.z), "f"(v.w) : "memory");
}

// ---------------- zero scratch ----------------
__global__ void k_zero() {
    int i = blockIdx.x * blockDim.x + threadIdx.x;
    float4 z = make_float4(0.f, 0.f, 0.f, 0.f);
    if (i < N_NODES * IN_DIM / 4) g_agg1[i] = z;
    if (i < N_NODES * OUT_DIM / 4) g_agg2[i] = z;
    if (i < N_NODES) g_cnt[i] = 0;
}

// ---------------- edge pass 1: scatter-add x[src] -> agg1[dst], degree count ----------------
__global__ void k_edge1(const float4* __restrict__ x4, const int* __restrict__ ei) {
    int idx = blockIdx.x * blockDim.x + threadIdx.x;
    if (idx >= N_EDGES * 32) return;
    int e = idx >> 5;
    int c = idx & 31;
    int s = __ldg(&ei[e]);
    int d = __ldg(&ei[N_EDGES + e]);
    float4 v = x4[(size_t)s * 32 + c];
    float* a = ((float*)g_agg1) + (size_t)d * IN_DIM + c * 4;
    red_add_v4(a, v);
    if (c == 0) atomicAdd(&g_cnt[d], 1);
}

__global__ void k_inv() {
    int i = blockIdx.x * blockDim.x + threadIdx.x;
    if (i < N_NODES) g_inv[i] = 1.0f / fmaxf((float)g_cnt[i], 1.0f);
}

// ---------------- GEMM1 (tensor): h = relu((agg1*inv)@W1l + x@W1r + b1) ----------------
// BM=128, BN=64, BK=16 (R13 shape). Linear tile loop with register prefetch:
// STS(t) -> sync -> LDG(t+1) -> compute(t) -> sync. LDG latency hides under MMAs.
__global__ __launch_bounds__(256) void k_gemm1(const float4* __restrict__ x4,
                                               const float4* __restrict__ W1l4,
                                               const float4* __restrict__ W1r4,
                                               const float4* __restrict__ b14) {
    __shared__ __align__(16) float As_hi[128][20], As_lo[128][20];  // 20KB
    __shared__ __align__(16) float Bs_hi[16][72], Bs_lo[16][72];    // 9KB

    int tid = threadIdx.x;
    int wid = tid >> 5, lane = tid & 31;
    int gid = lane >> 2, tig = lane & 3;
    int rowBase = blockIdx.y * 128;
    int colBase = blockIdx.x * 64;
    int warpM = (wid >> 1) * 32;
    int warpN = (wid & 1) * 32;

    // A loader: two fixed slots (r0,q0) and (r0+64,q0)
    int r0 = tid >> 2, q0 = tid & 3;
    int r1 = r0 + 64;
    int arow0 = rowBase + r0, arow1 = rowBase + r1;
    bool aok0 = arow0 < N_NODES, aok1 = arow1 < N_NODES;
    float sc0 = aok0 ? g_inv[arow0] : 0.f;
    float sc1 = aok1 ? g_inv[arow1] : 0.f;
    // B loader: fixed (bk, bc4)
    int bk = tid >> 4, bc4 = tid & 15;

    float acc[2][4][4];
#pragma unroll
    for (int mt = 0; mt < 2; mt++)
#pragma unroll
        for (int nt = 0; nt < 4; nt++)
#pragma unroll
            for (int i = 0; i < 4; i++) acc[mt][nt][i] = 0.f;

    const float4 fz = make_float4(0.f, 0.f, 0.f, 0.f);
    // prefetch tile 0 (phase 0, kt = 0)
    float4 pa0 = aok0 ? g_agg1[(size_t)arow0 * 32 + q0] : fz;
    float4 pa1 = aok1 ? g_agg1[(size_t)arow1 * 32 + q0] : fz;
    float4 pb  = W1l4[(size_t)bk * 64 + (colBase >> 2) + bc4];

    for (int t = 0; t < 16; ++t) {
        int phase = t >> 3;
        // ---- stage staged regs into SMEM (scale on phase 0, split hi/lo) ----
        {
            float4 va0 = pa0, va1 = pa1, wb = pb;
            if (phase == 0) {
                va0.x *= sc0; va0.y *= sc0; va0.z *= sc0; va0.w *= sc0;
                va1.x *= sc1; va1.y *= sc1; va1.z *= sc1; va1.w *= sc1;
            }
            float h0, l0, h1, l1, h2, l2, h3, l3;
            int kb = q0 * 4;
            tf32_split(va0.x, h0, l0); tf32_split(va0.y, h1, l1);
            tf32_split(va0.z, h2, l2); tf32_split(va0.w, h3, l3);
            *(float4*)&As_hi[r0][kb] = make_float4(h0, h1, h2, h3);
            *(float4*)&As_lo[r0][kb] = make_float4(l0, l1, l2, l3);
            tf32_split(va1.x, h0, l0); tf32_split(va1.y, h1, l1);
            tf32_split(va1.z, h2, l2); tf32_split(va1.w, h3, l3);
            *(float4*)&As_hi[r1][kb] = make_float4(h0, h1, h2, h3);
            *(float4*)&As_lo[r1][kb] = make_float4(l0, l1, l2, l3);
            int nb = bc4 * 4;
            tf32_split(wb.x, h0, l0); tf32_split(wb.y, h1, l1);
            tf32_split(wb.z, h2, l2); tf32_split(wb.w, h3, l3);
            *(float4*)&Bs_hi[bk][nb] = make_float4(h0, h1, h2, h3);
            *(float4*)&Bs_lo[bk][nb] = make_float4(l0, l1, l2, l3);
        }
        __syncthreads();
        // ---- prefetch next tile (LDG overlaps the MMA compute below) ----
        if (t < 15) {
            int tn = t + 1;
            int ph = tn >> 3;
            int ktn = (tn & 7) * 16;
            const float4* A4 = ph ? x4 : g_agg1;
            const float4* W4 = ph ? W1r4 : W1l4;
            pa0 = aok0 ? A4[(size_t)arow0 * 32 + (ktn >> 2) + q0] : fz;
            pa1 = aok1 ? A4[(size_t)arow1 * 32 + (ktn >> 2) + q0] : fz;
            pb  = W4[(size_t)(ktn + bk) * 64 + (colBase >> 2) + bc4];
        }
        // ---- compute ----
#pragma unroll
        for (int s = 0; s < 2; s++) {
            int k0 = s * 8 + tig;
            unsigned ah[8], al[8], bh[8], bl[8];
#pragma unroll
            for (int mt = 0; mt < 2; mt++) {
                int m0 = warpM + mt * 16 + gid;
                ah[mt*4+0] = __float_as_uint(As_hi[m0][k0]);
                ah[mt*4+1] = __float_as_uint(As_hi[m0 + 8][k0]);
                ah[mt*4+2] = __float_as_uint(As_hi[m0][k0 + 4]);
                ah[mt*4+3] = __float_as_uint(As_hi[m0 + 8][k0 + 4]);
                al[mt*4+0] = __float_as_uint(As_lo[m0][k0]);
                al[mt*4+1] = __float_as_uint(As_lo[m0 + 8][k0]);
                al[mt*4+2] = __float_as_uint(As_lo[m0][k0 + 4]);
                al[mt*4+3] = __float_as_uint(As_lo[m0 + 8][k0 + 4]);
            }
#pragma unroll
            for (int nt = 0; nt < 4; nt++) {
                int n0 = warpN + nt * 8 + gid;
                bh[nt*2+0] = __float_as_uint(Bs_hi[k0][n0]);
                bh[nt*2+1] = __float_as_uint(Bs_hi[k0 + 4][n0]);
                bl[nt*2+0] = __float_as_uint(Bs_lo[k0][n0]);
                bl[nt*2+1] = __float_as_uint(Bs_lo[k0 + 4][n0]);
            }
#pragma unroll
            for (int mt = 0; mt < 2; mt++)
#pragma unroll
                for (int nt = 0; nt < 4; nt++) {
                    float* c = acc[mt][nt];
                    mma_tf32(c, &ah[mt * 4], &bh[nt * 2]);  // hi*hi
                    mma_tf32(c, &ah[mt * 4], &bl[nt * 2]);  // hi*lo
                    mma_tf32(c, &al[mt * 4], &bh[nt * 2]);  // lo*hi
                }
        }
        __syncthreads();
    }

    // epilogue: bias + relu, float2 stores
#pragma unroll
    for (int mt = 0; mt < 2; mt++) {
#pragma unroll
        for (int nt = 0; nt < 4; nt++) {
            int rr = rowBase + warpM + mt * 16 + gid;
            int col = colBase + warpN + nt * 8 + 2 * tig;
            float2 bb = *(const float2*)((const float*)b14 + col);
            const float* c = acc[mt][nt];
            if (rr < N_NODES) {
                float2 o = make_float2(fmaxf(c[0] + bb.x, 0.f), fmaxf(c[1] + bb.y, 0.f));
                *(float2*)(((float*)g_h) + (size_t)rr * HID_DIM + col) = o;
            }
            if (rr + 8 < N_NODES) {
                float2 o = make_float2(fmaxf(c[2] + bb.x, 0.f), fmaxf(c[3] + bb.y, 0.f));
                *(float2*)(((float*)g_h) + (size_t)(rr + 8) * HID_DIM + col) = o;
            }
        }
    }
}

// ---------------- GEMM2 (tensor): pq = h @ [W2l | W2r]  (N x 80, K=256) ----------------
// BM=128, BN=80, BK=16, register-prefetch pipeline like gemm1.
__global__ __launch_bounds__(256) void k_gemm2(const float4* __restrict__ W2l4,
                                               const float4* __restrict__ W2r4) {
    __shared__ __align__(16) float As_hi[128][20], As_lo[128][20];  // 20KB
    __shared__ __align__(16) float Bs_hi[16][88], Bs_lo[16][88];    // 11KB

    int tid = threadIdx.x;
    int wid = tid >> 5, lane = tid & 31;
    int gid = lane >> 2, tig = lane & 3;
    int rowBase = blockIdx.y * 128;
    int warpM = (wid >> 1) * 32;
    int warpN = (wid & 1) * 40;

    // A loader fixed coords
    int r0 = tid >> 2, q0 = tid & 3;
    int r1 = r0 + 64;
    int arow0 = rowBase + r0, arow1 = rowBase + r1;
    bool aok0 = arow0 < N_NODES, aok1 = arow1 < N_NODES;
    // B loader: slot0 = tid (<320), slot1 = tid+256 (only tid<64)
    int bk0 = tid / 20, bc0 = tid % 20;
    int bk1 = (tid + 256) / 20, bc1 = (tid + 256) % 20;
    bool bok1 = tid < 64;

    float acc[2][5][4];
#pragma unroll
    for (int mt = 0; mt < 2; mt++)
#pragma unroll
        for (int nt = 0; nt < 5; nt++)
#pragma unroll
            for (int i = 0; i < 4; i++) acc[mt][nt][i] = 0.f;

    const float4 fz = make_float4(0.f, 0.f, 0.f, 0.f);
    auto loadB = [&](int kt, int bk, int bc) -> float4 {
        if (bc < 10) return W2l4[(size_t)(kt + bk) * 10 + bc];
        return W2r4[(size_t)(kt + bk) * 10 + (bc - 10)];
    };
    // prefetch tile 0
    float4 pa0 = aok0 ? g_h[(size_t)arow0 * 64 + q0] : fz;
    float4 pa1 = aok1 ? g_h[(size_t)arow1 * 64 + q0] : fz;
    float4 pb0 = loadB(0, bk0, bc0);
    float4 pb1 = bok1 ? loadB(0, bk1, bc1) : fz;

    for (int t = 0; t < 16; ++t) {
        // ---- stage ----
        {
            float h0, l0, h1, l1, h2, l2, h3, l3;
            int kb = q0 * 4;
            tf32_split(pa0.x, h0, l0); tf32_split(pa0.y, h1, l1);
            tf32_split(pa0.z, h2, l2); tf32_split(pa0.w, h3, l3);
            *(float4*)&As_hi[r0][kb] = make_float4(h0, h1, h2, h3);
            *(float4*)&As_lo[r0][kb] = make_float4(l0, l1, l2, l3);
            tf32_split(pa1.x, h0, l0); tf32_split(pa1.y, h1, l1);
            tf32_split(pa1.z, h2, l2); tf32_split(pa1.w, h3, l3);
            *(float4*)&As_hi[r1][kb] = make_float4(h0, h1, h2, h3);
            *(float4*)&As_lo[r1][kb] = make_float4(l0, l1, l2, l3);
            int nb = bc0 * 4;
            tf32_split(pb0.x, h0, l0); tf32_split(pb0.y, h1, l1);
            tf32_split(pb0.z, h2, l2); tf32_split(pb0.w, h3, l3);
            *(float4*)&Bs_hi[bk0][nb] = make_float4(h0, h1, h2, h3);
            *(float4*)&Bs_lo[bk0][nb] = make_float4(l0, l1, l2, l3);
            if (bok1) {
                nb = bc1 * 4;
                tf32_split(pb1.x, h0, l0); tf32_split(pb1.y, h1, l1);
                tf32_split(pb1.z, h2, l2); tf32_split(pb1.w, h3, l3);
                *(float4*)&Bs_hi[bk1][nb] = make_float4(h0, h1, h2, h3);
                *(float4*)&Bs_lo[bk1][nb] = make_float4(l0, l1, l2, l3);
            }
        }
        __syncthreads();
        // ---- prefetch next ----
        if (t < 15) {
            int ktn = (t + 1) * 16;
            pa0 = aok0 ? g_h[(size_t)arow0 * 64 + (ktn >> 2) + q0] : fz;
            pa1 = aok1 ? g_h[(size_t)arow1 * 64 + (ktn >> 2) + q0] : fz;
            pb0 = loadB(ktn, bk0, bc0);
            pb1 = bok1 ? loadB(ktn, bk1, bc1) : fz;
        }
        // ---- compute ----
#pragma unroll
        for (int s = 0; s < 2; s++) {
            int k0 = s * 8 + tig;
            unsigned ah[8], al[8], bh[10], bl[10];
#pragma unroll
            for (int mt = 0; mt < 2; mt++) {
                int m0 = warpM + mt * 16 + gid;
                ah[mt*4+0] = __float_as_uint(As_hi[m0][k0]);
                ah[mt*4+1] = __float_as_uint(As_hi[m0 + 8][k0]);
                ah[mt*4+2] = __float_as_uint(As_hi[m0][k0 + 4]);
                ah[mt*4+3] = __float_as_uint(As_hi[m0 + 8][k0 + 4]);
                al[mt*4+0] = __float_as_uint(As_lo[m0][k0]);
                al[mt*4+1] = __float_as_uint(As_lo[m0 + 8][k0]);
                al[mt*4+2] = __float_as_uint(As_lo[m0][k0 + 4]);
                al[mt*4+3] = __float_as_uint(As_lo[m0 + 8][k0 + 4]);
            }
#pragma unroll
            for (int nt = 0; nt < 5; nt++) {
                int n0 = warpN + nt * 8 + gid;
                bh[nt*2+0] = __float_as_uint(Bs_hi[k0][n0]);
                bh[nt*2+1] = __float_as_uint(Bs_hi[k0 + 4][n0]);
                bl[nt*2+0] = __float_as_uint(Bs_lo[k0][n0]);
                bl[nt*2+1] = __float_as_uint(Bs_lo[k0 + 4][n0]);
            }
#pragma unroll
            for (int mt = 0; mt < 2; mt++)
#pragma unroll
                for (int nt = 0; nt < 5; nt++) {
                    float* c = acc[mt][nt];
                    mma_tf32(c, &ah[mt * 4], &bh[nt * 2]);
                    mma_tf32(c, &ah[mt * 4], &bl[nt * 2]);
                    mma_tf32(c, &al[mt * 4], &bh[nt * 2]);
                }
        }
        __syncthreads();
    }

#pragma unroll
    for (int mt = 0; mt < 2; mt++) {
#pragma unroll
        for (int nt = 0; nt < 5; nt++) {
            int rr = rowBase + warpM + mt * 16 + gid;
            int col = warpN + nt * 8 + 2 * tig;   // 0..79 within [p|q]
            const float* c = acc[mt][nt];
            if (rr < N_NODES)
                *(float2*)(((float*)g_pq) + (size_t)rr * 80 + col) = make_float2(c[0], c[1]);
            if (rr + 8 < N_NODES)
                *(float2*)(((float*)g_pq) + (size_t)(rr + 8) * 80 + col) = make_float2(c[2], c[3]);
        }
    }
}

// ---------------- edge pass 2: scatter-add p[src] -> agg2[dst] (40 floats) ----------------
__global__ void k_scatter2(const int* __restrict__ ei) {
    int idx = blockIdx.x * blockDim.x + threadIdx.x;
    if (idx >= N_EDGES * 10) return;
    int e = idx / 10;
    int c = idx % 10;
    int s = __ldg(&ei[e]);
    int d = __ldg(&ei[N_EDGES + e]);
    float4 v = g_pq[(size_t)s * 20 + c];  // p half = f4 slots 0..9
    float* a = ((float*)g_agg2) + (size_t)d * OUT_DIM + c * 4;
    red_add_v4(a, v);
}

// ---------------- finalize: out = agg2*inv + b2 + q ----------------
__global__ void k_final(const float4* __restrict__ b24, float4* __restrict__ out4) {
    int idx = blockIdx.x * blockDim.x + threadIdx.x;
    if (idx >= N_NODES * 10) return;
    int row = idx / 10;
    int c = idx % 10;
    float inv = g_inv[row];
    float4 ag = g_agg2[(size_t)row * 10 + c];
    float4 q = g_pq[(size_t)row * 20 + 10 + c];  // q half = f4 slots 10..19
    float4 b = b24[c];
    float4 o;
    o.x = ag.x * inv + b.x + q.x;
    o.y = ag.y * inv + b.y + q.y;
    o.z = ag.z * inv + b.z + q.z;
    o.w = ag.w * inv + b.w + q.w;
    out4[idx] = o;
}

// ---------------- launch ----------------
extern "C" void kernel_launch(void* const* d_in, const int* in_sizes, int n_in,
                              void* d_out, int out_size) {
    const float4* x4 = (const float4*)d_in[0];
    const int* ei = (const int*)d_in[1];   // int32 (JAX x64 disabled)
    const float4* W1l4 = (const float4*)d_in[2];
    const float4* b14 = (const float4*)d_in[3];
    const float4* W1r4 = (const float4*)d_in[4];
    const float4* W2l4 = (const float4*)d_in[5];
    const float4* b24 = (const float4*)d_in[6];
    const float4* W2r4 = (const float4*)d_in[7];
    float4* out4 = (float4*)d_out;

    k_zero<<<(N_NODES * IN_DIM / 4 + 255) / 256, 256>>>();
    k_edge1<<<(N_EDGES * 32 + 255) / 256, 256>>>(x4, ei);
    k_inv<<<(N_NODES + 255) / 256, 256>>>();
    dim3 g1(HID_DIM / 64, (N_NODES + 127) / 128);   // 4 x 782
    k_gemm1<<<g1, 256>>>(x4, W1l4, W1r4, b14);
    dim3 g2(1, (N_NODES + 127) / 128);
    k_gemm2<<<g2, 256>>>(W2l4, W2r4);
    k_scatter2<<<(N_EDGES * 10 + 255) / 256, 256>>>(ei);
    k_final<<<(N_NODES * 10 + 255) / 256, 256>>>(b24, out4);
}